// round 16
// baseline (speedup 1.0000x reference)
#include <cuda_runtime.h>
#include <cuda_fp16.h>
#include <cuda_bf16.h>
#include <math_constants.h>
#include <cstdint>

#define F_IN 116
#define H 8
#define C 32
#define HC 256           // H*C
#define MAXN 50016
#define MAXE 1000000
#define NEG_SLOPE 0.2f
#define MROWS 64         // gemm rows per block (2 m-tiles per warp)
#define XSW 132          // padded xs row (floats)
#define SCHUNK 2048      // scan chunk per block

// ---------------- device scratch (no allocations allowed) ----------------
__device__ __align__(16) __half g_xt_h[(size_t)MAXN * HC]; // fp16 features; row N stays 0 (sentinel)
__device__ __align__(16) float g_as[(size_t)MAXN * H];     // alpha_src (row N = -inf sentinel)
__device__ __align__(16) float g_ad[(size_t)MAXN * H];     // alpha_dst
__device__ __align__(16) uint4 g_Wb4[8][32][32];           // W fragments {bh.x,bh.y,bl.x,bl.y}
__device__ __align__(16) int g_deg[MAXN];
__device__ int g_off[MAXN + 1];                            // aligned (ceil4) offsets
__device__ int g_cur[MAXN];
__device__ __align__(16) int g_csr[MAXE];                  // src ids grouped by dst, pad slots = N
__device__ int g_idx64_unused;

// ---------------- side stream + events ----------------
struct HxStreams {
    cudaStream_t s2;
    cudaEvent_t evFork, evJoin;
    HxStreams() {
        cudaStreamCreateWithFlags(&s2, cudaStreamNonBlocking);
        cudaEventCreateWithFlags(&evFork, cudaEventDisableTiming);
        cudaEventCreateWithFlags(&evJoin, cudaEventDisableTiming);
    }
};
static HxStreams g_hx;

__device__ __forceinline__ uint32_t packbf(float a, float b) {
    uint32_t r;
    asm("cvt.rn.bf16x2.f32 %0, %1, %2;" : "=r"(r) : "f"(b), "f"(a));
    return r;
}
__device__ __forceinline__ float bf_lo_f(uint32_t u) { return __uint_as_float(u << 16); }
__device__ __forceinline__ float bf_hi_f(uint32_t u) { return __uint_as_float(u & 0xffff0000u); }

// per-block idx-width detection (64 reads, L1-broadcast; no cross-kernel dep)
__device__ __forceinline__ int detect_idx64(const int* ei32, int n_check, int* s_is64) {
    if (threadIdx.x == 0) {
        int is64 = 1;
        for (int k = 0; k < n_check; k++)
            if (ei32[2 * k + 1] != 0) { is64 = 0; break; }
        *s_is64 = is64;
    }
    __syncthreads();
    return *s_is64;
}

// ---------------- zero: deg zeros + sentinel alpha row ----------------
__global__ void zero_kernel(int N) {
    int i = blockIdx.x * blockDim.x + threadIdx.x;
    if (i < N) g_deg[i] = 0;
    if (i == N) {
#pragma unroll
        for (int h = 0; h < H; h++) g_as[(size_t)N * H + h] = -CUDART_INF_F;
    }
}

// ---------------- wpack: W bf16-split uint4 fragment pack (side stream) ----------------
__global__ void wpack_kernel(const float* __restrict__ W) {
    int i = blockIdx.x * blockDim.x + threadIdx.x;
    if (i >= 8192) return;
    int ks = i >> 10;
    int rem = i & 1023;
    int gnt = rem >> 5;
    int lane = rem & 31;
    int g = lane >> 2, tig = lane & 3;
    int n = gnt * 8 + g;
    int k0 = ks * 16 + tig * 2;
    float w00 = (k0     < F_IN) ? W[(k0)     * HC + n] : 0.0f;
    float w01 = (k0 + 1 < F_IN) ? W[(k0 + 1) * HC + n] : 0.0f;
    float w10 = (k0 + 8 < F_IN) ? W[(k0 + 8) * HC + n] : 0.0f;
    float w11 = (k0 + 9 < F_IN) ? W[(k0 + 9) * HC + n] : 0.0f;
    uint32_t h0 = packbf(w00, w01);
    uint32_t h1 = packbf(w10, w11);
    uint32_t l0 = packbf(w00 - bf_lo_f(h0), w01 - bf_hi_f(h0));
    uint32_t l1 = packbf(w10 - bf_lo_f(h1), w11 - bf_hi_f(h1));
    g_Wb4[ks][gnt][lane] = make_uint4(h0, h1, l0, l1);
}

// ---------------- count in-degrees (dst half only, per-block detect) ----------------
__global__ void count_kernel(const void* __restrict__ ei, int E, int n_check) {
    __shared__ int s_is64;
    int idx64 = detect_idx64((const int*)ei, n_check, &s_is64);
    int i = blockIdx.x * blockDim.x + threadIdx.x;
    if (i >= E) return;
    int dst;
    if (idx64) dst = (int)((const long long*)ei)[(size_t)E + i];
    else       dst = ((const int*)ei)[E + i];
    atomicAdd(&g_deg[dst], 1);
}

// ---------------- single-kernel exclusive scan of ceil4(deg) -> g_off, g_cur ----------------
__device__ __forceinline__ int ceil4(int v) { return (v + 3) & ~3; }

__global__ void scan_kernel(int N) {
    __shared__ int sm[256];
    int b0 = blockIdx.x * SCHUNK;
    int t = threadIdx.x;

    int base_p = 0;
    for (int i = t * 4; i < b0; i += 1024) {
        int4 d = *(const int4*)&g_deg[i];
        base_p += ceil4(d.x) + ceil4(d.y) + ceil4(d.z) + ceil4(d.w);
    }
    sm[t] = base_p;
    __syncthreads();
    for (int o = 128; o > 0; o >>= 1) {
        if (t < o) sm[t] += sm[t + o];
        __syncthreads();
    }
    int base = sm[0];
    __syncthreads();

    const int PT = SCHUNK / 256;
    int cbase = b0 + t * PT;
    int loc[PT];
    int s = 0;
#pragma unroll
    for (int k = 0; k < PT; k++) {
        int i = cbase + k;
        loc[k] = s;
        if (i < N) s += ceil4(g_deg[i]);
    }
    sm[t] = s;
    __syncthreads();
    for (int o = 1; o < 256; o <<= 1) {
        int v = (t >= o) ? sm[t - o] : 0;
        __syncthreads();
        sm[t] += v;
        __syncthreads();
    }
    int tbase = base + ((t > 0) ? sm[t - 1] : 0);
#pragma unroll
    for (int k = 0; k < PT; k++) {
        int i = cbase + k;
        if (i < N) {
            int o = tbase + loc[k];
            g_off[i] = o;
            g_cur[i] = o;
            int d = g_deg[i];
            int c4 = ceil4(d);
            for (int q = d; q < c4; q++) g_csr[o + q] = N;
        }
    }
    if (blockIdx.x == gridDim.x - 1 && t == 255) g_off[N] = base + sm[255];
}

// ---------------- scatter src ids into CSR slots (per-block detect) ----------------
__global__ void scatter_kernel(const void* __restrict__ ei, int E, int n_check) {
    __shared__ int s_is64;
    int idx64 = detect_idx64((const int*)ei, n_check, &s_is64);
    int i = blockIdx.x * blockDim.x + threadIdx.x;
    if (i >= E) return;
    int src, dst;
    if (idx64) {
        const long long* p = (const long long*)ei;
        src = (int)p[i];
        dst = (int)p[(size_t)E + i];
    } else {
        const int* p = (const int*)ei;
        src = p[i];
        dst = p[E + i];
    }
    int pos = atomicAdd(&g_cur[dst], 1);
    g_csr[pos] = src;
}

// ---------------- gemm: HMMA bf16 2-term split, in-register conversion (R14) + uint4 W ----------------
__device__ __forceinline__ void mma_bf16(float* d, uint32_t a0, uint32_t a1, uint32_t a2, uint32_t a3,
                                         uint32_t b0, uint32_t b1) {
    asm("mma.sync.aligned.m16n8k16.row.col.f32.bf16.bf16.f32 "
        "{%0,%1,%2,%3}, {%4,%5,%6,%7}, {%8,%9}, {%0,%1,%2,%3};"
        : "+f"(d[0]), "+f"(d[1]), "+f"(d[2]), "+f"(d[3])
        : "r"(a0), "r"(a1), "r"(a2), "r"(a3), "r"(b0), "r"(b1));
}

__global__ void __launch_bounds__(256, 2)
gemm_alpha_kernel(const float* __restrict__ x,
                  const float* __restrict__ att_src,
                  const float* __restrict__ att_dst,
                  int N) {
    __shared__ __align__(16) float xs[MROWS][XSW];
    int t = threadIdx.x;
    int w = t >> 5, lane = t & 31;
    int g = lane >> 2, tig = lane & 3;
    int mw = w >> 2, nw = w & 3;
    int row0 = blockIdx.x * MROWS;

    for (int i = t; i < MROWS * 128; i += 256) {
        int r = i >> 7, c = i & 127;
        int gr = row0 + r;
        xs[r][c] = (c < F_IN && gr < N) ? x[(size_t)gr * F_IN + c] : 0.0f;
    }
    __syncthreads();

    float d[2][8][4];
#pragma unroll
    for (int mt = 0; mt < 2; mt++)
#pragma unroll
        for (int nt = 0; nt < 8; nt++)
#pragma unroll
            for (int q = 0; q < 4; q++) d[mt][nt][q] = 0.0f;

    int ra0 = mw * 32 + g;       // mt=0 rows: ra0, ra0+8; mt=1: ra0+16, ra0+24

#pragma unroll
    for (int ks = 0; ks < 8; ks++) {
        int k0 = ks * 16 + tig * 2;
        uint32_t ah[2][4], al[2][4];
#pragma unroll
        for (int mt = 0; mt < 2; mt++) {
            int ra = ra0 + mt * 16;
            float2 xa = *(const float2*)&xs[ra][k0];
            float2 xb = *(const float2*)&xs[ra + 8][k0];
            float2 xc = *(const float2*)&xs[ra][k0 + 8];
            float2 xd = *(const float2*)&xs[ra + 8][k0 + 8];
            ah[mt][0] = packbf(xa.x, xa.y);
            ah[mt][1] = packbf(xb.x, xb.y);
            ah[mt][2] = packbf(xc.x, xc.y);
            ah[mt][3] = packbf(xd.x, xd.y);
            al[mt][0] = packbf(xa.x - bf_lo_f(ah[mt][0]), xa.y - bf_hi_f(ah[mt][0]));
            al[mt][1] = packbf(xb.x - bf_lo_f(ah[mt][1]), xb.y - bf_hi_f(ah[mt][1]));
            al[mt][2] = packbf(xc.x - bf_lo_f(ah[mt][2]), xc.y - bf_hi_f(ah[mt][2]));
            al[mt][3] = packbf(xd.x - bf_lo_f(ah[mt][3]), xd.y - bf_hi_f(ah[mt][3]));
        }
#pragma unroll
        for (int nt = 0; nt < 8; nt++) {
            uint4 bw = g_Wb4[ks][nw * 8 + nt][lane];
#pragma unroll
            for (int mt = 0; mt < 2; mt++) {
                mma_bf16(d[mt][nt], ah[mt][0], ah[mt][1], ah[mt][2], ah[mt][3], bw.x, bw.y); // ah*bh
                mma_bf16(d[mt][nt], ah[mt][0], ah[mt][1], ah[mt][2], ah[mt][3], bw.z, bw.w); // ah*bl
                mma_bf16(d[mt][nt], al[mt][0], al[mt][1], al[mt][2], al[mt][3], bw.x, bw.y); // al*bh
            }
        }
    }

    // epilogue: fp16 xt stores + per-(row, head) alpha partials, per m-tile
    __half2* xt2 = (__half2*)g_xt_h;
    float pS[2][2][2] = {};   // [mt][rowsel][headsel]
    float pD[2][2][2] = {};

#pragma unroll
    for (int nt = 0; nt < 8; nt++) {
        int col = nw * 64 + nt * 8 + tig * 2;
        int hs = nt >> 2;
        float s0 = __ldg(&att_src[col]);
        float s1 = __ldg(&att_src[col + 1]);
        float t0 = __ldg(&att_dst[col]);
        float t1 = __ldg(&att_dst[col + 1]);
#pragma unroll
        for (int mt = 0; mt < 2; mt++) {
            int gr0 = row0 + ra0 + mt * 16;
            int gr1 = gr0 + 8;
            pS[mt][0][hs] += d[mt][nt][0] * s0 + d[mt][nt][1] * s1;
            pS[mt][1][hs] += d[mt][nt][2] * s0 + d[mt][nt][3] * s1;
            pD[mt][0][hs] += d[mt][nt][0] * t0 + d[mt][nt][1] * t1;
            pD[mt][1][hs] += d[mt][nt][2] * t0 + d[mt][nt][3] * t1;
            if (gr0 < N) xt2[(size_t)gr0 * 128 + (col >> 1)] = __floats2half2_rn(d[mt][nt][0], d[mt][nt][1]);
            if (gr1 < N) xt2[(size_t)gr1 * 128 + (col >> 1)] = __floats2half2_rn(d[mt][nt][2], d[mt][nt][3]);
        }
    }

#pragma unroll
    for (int mt = 0; mt < 2; mt++)
#pragma unroll
        for (int rs = 0; rs < 2; rs++)
#pragma unroll
            for (int hsl = 0; hsl < 2; hsl++) {
                float v1 = pS[mt][rs][hsl];
                v1 += __shfl_xor_sync(0xffffffffu, v1, 1);
                v1 += __shfl_xor_sync(0xffffffffu, v1, 2);
                pS[mt][rs][hsl] = v1;
                float v2 = pD[mt][rs][hsl];
                v2 += __shfl_xor_sync(0xffffffffu, v2, 1);
                v2 += __shfl_xor_sync(0xffffffffu, v2, 2);
                pD[mt][rs][hsl] = v2;
            }

    if (tig == 0) {
#pragma unroll
        for (int mt = 0; mt < 2; mt++)
#pragma unroll
            for (int rs = 0; rs < 2; rs++) {
                int gr = row0 + ra0 + mt * 16 + rs * 8;
                if (gr < N) {
#pragma unroll
                    for (int hsl = 0; hsl < 2; hsl++) {
                        int h = nw * 2 + hsl;
                        g_as[(size_t)gr * H + h] = pS[mt][rs][hsl];
                        g_ad[(size_t)gr * H + h] = pD[mt][rs][hsl];
                    }
                }
            }
    }
}

// ---------------- fused gather-aggregate + softmax + head-mean + bias + relu ----------------
__device__ __forceinline__ void acc_row(const float4& raw, float ev, float* acc) {
    const __half2* hp = (const __half2*)&raw;
    float2 f0 = __half22float2(hp[0]);
    float2 f1 = __half22float2(hp[1]);
    float2 f2 = __half22float2(hp[2]);
    float2 f3 = __half22float2(hp[3]);
    acc[0] = fmaf(ev, f0.x, acc[0]); acc[1] = fmaf(ev, f0.y, acc[1]);
    acc[2] = fmaf(ev, f1.x, acc[2]); acc[3] = fmaf(ev, f1.y, acc[3]);
    acc[4] = fmaf(ev, f2.x, acc[4]); acc[5] = fmaf(ev, f2.y, acc[5]);
    acc[6] = fmaf(ev, f3.x, acc[6]); acc[7] = fmaf(ev, f3.y, acc[7]);
}

__global__ void agg_kernel(const float* __restrict__ bias,
                           float* __restrict__ out, int N) {
    int gw = (blockIdx.x * blockDim.x + threadIdx.x) >> 5;
    int lane = threadIdx.x & 31;
    if (gw >= N) return;
    int n = gw;
    int h = lane >> 2;

    const char* asb = (const char*)g_as;
    const char* xtb = (const char*)g_xt_h;
    int hoff = h << 2;
    int loff = lane << 4;

    float ad_h = g_ad[(size_t)n * H + h];

    float a = *(const float*)(asb + (((unsigned)n << 5) + hoff)) + ad_h;
    a = (a > 0.0f) ? a : NEG_SLOPE * a;
    float e = __expf(a);
    float s = e;

    float acc[8] = {0, 0, 0, 0, 0, 0, 0, 0};
    {
        float4 raw = *(const float4*)(xtb + ((unsigned)n << 9) + loff);
        acc_row(raw, e, acc);
    }

    int beg = g_off[n];
    int end = g_off[n + 1];
    for (int p = beg; p < end; p += 4) {
        int4 sv = *(const int4*)(g_csr + p);
        float a0 = *(const float*)(asb + (((unsigned)sv.x << 5) + hoff)) + ad_h;
        float a1 = *(const float*)(asb + (((unsigned)sv.y << 5) + hoff)) + ad_h;
        float a2 = *(const float*)(asb + (((unsigned)sv.z << 5) + hoff)) + ad_h;
        float a3 = *(const float*)(asb + (((unsigned)sv.w << 5) + hoff)) + ad_h;
        a0 = (a0 > 0.0f) ? a0 : NEG_SLOPE * a0;
        a1 = (a1 > 0.0f) ? a1 : NEG_SLOPE * a1;
        a2 = (a2 > 0.0f) ? a2 : NEG_SLOPE * a2;
        a3 = (a3 > 0.0f) ? a3 : NEG_SLOPE * a3;
        float e0 = __expf(a0);
        float e1 = __expf(a1);
        float e2 = __expf(a2);
        float e3 = __expf(a3);
        s += (e0 + e1) + (e2 + e3);
        float4 r0 = *(const float4*)(xtb + ((unsigned)sv.x << 9) + loff);
        float4 r1 = *(const float4*)(xtb + ((unsigned)sv.y << 9) + loff);
        float4 r2 = *(const float4*)(xtb + ((unsigned)sv.z << 9) + loff);
        float4 r3 = *(const float4*)(xtb + ((unsigned)sv.w << 9) + loff);
        acc_row(r0, e0, acc);
        acc_row(r1, e1, acc);
        acc_row(r2, e2, acc);
        acc_row(r3, e3, acc);
    }

    float inv = 1.0f / (s + 1e-16f);
    float r[8];
#pragma unroll
    for (int i = 0; i < 8; i++) r[i] = acc[i] * inv;

#pragma unroll
    for (int i = 0; i < 8; i++) {
        r[i] += __shfl_xor_sync(0xffffffffu, r[i], 4);
        r[i] += __shfl_xor_sync(0xffffffffu, r[i], 8);
        r[i] += __shfl_xor_sync(0xffffffffu, r[i], 16);
    }

    if (lane < 4) {
        float o[8];
#pragma unroll
        for (int i = 0; i < 8; i++) {
            float v = r[i] * 0.125f + bias[lane * 8 + i];
            o[i] = (v > 0.0f) ? v : 0.0f;
        }
        float4* orow = (float4*)(out + (size_t)n * C + lane * 8);
        orow[0] = make_float4(o[0], o[1], o[2], o[3]);
        orow[1] = make_float4(o[4], o[5], o[6], o[7]);
    }
}

// ---------------- launch: zero, count || (wpack, gemm), scan, scatter, agg ----------------
extern "C" void kernel_launch(void* const* d_in, const int* in_sizes, int n_in,
                              void* d_out, int out_size) {
    const float* x       = (const float*)d_in[0];
    const void*  ei      = d_in[1];
    const float* W       = (const float*)d_in[2];
    const float* att_src = (const float*)d_in[3];
    const float* att_dst = (const float*)d_in[4];
    const float* bias    = (const float*)d_in[5];

    int N = in_sizes[0] / F_IN;
    int E = in_sizes[1] / 2;
    int n_check = E > 64 ? 64 : E;

    // fork side stream immediately — wpack+gemm run concurrent with the CSR chain
    cudaEventRecord(g_hx.evFork, 0);
    cudaStreamWaitEvent(g_hx.s2, g_hx.evFork, 0);

    // (1) zero (main): deg zeros + sentinel alpha row
    zero_kernel<<<(N + 256) / 256, 256>>>(N);

    // (2) count (main)
    count_kernel<<<(E + 255) / 256, 256>>>(ei, E, n_check);

    // (3) wpack, (4) gemm  [side stream — gemm in profile slot 4]
    wpack_kernel<<<32, 256, 0, g_hx.s2>>>(W);
    gemm_alpha_kernel<<<(N + MROWS - 1) / MROWS, 256, 0, g_hx.s2>>>(x, att_src, att_dst, N);
    cudaEventRecord(g_hx.evJoin, g_hx.s2);

    // (5) scan, (6) scatter  [main]
    int NB = (N + SCHUNK - 1) / SCHUNK;
    scan_kernel<<<NB, 256>>>(N);
    scatter_kernel<<<(E + 255) / 256, 256>>>(ei, E, n_check);

    // (7) aggregate (joins gemm)
    cudaStreamWaitEvent(0, g_hx.evJoin, 0);
    agg_kernel<<<(N + 7) / 8, 256>>>(bias, (float*)d_out, N);
}

// round 17
// speedup vs baseline: 1.0977x; 1.0977x over previous
#include <cuda_runtime.h>
#include <cuda_fp16.h>
#include <math_constants.h>
#include <cstdint>

#define F_IN 116
#define H 8
#define C 32
#define HC 256           // H*C
#define MAXN 50016
#define MAXE 1000000
#define NEG_SLOPE 0.2f
#define MROWS 64         // gemm rows per block (2 m-tiles per warp)
#define XSW 132          // padded xs row (floats)
#define SCHUNK 2048      // scan chunk per block

// ---------------- device scratch (no allocations allowed) ----------------
__device__ __align__(16) __half g_xt_h[(size_t)MAXN * HC]; // fp16 features; row N stays 0 (sentinel)
__device__ __align__(16) float g_as[(size_t)MAXN * H];     // alpha_src (row N = -inf sentinel)
__device__ __align__(16) float g_ad[(size_t)MAXN * H];     // alpha_dst
__device__ __align__(16) uint2 g_Wh[8][32][32];            // W fp16 fragments {h0,h1} [ks][ntile][lane]
__device__ __align__(16) int g_deg[MAXN];
__device__ int g_off[MAXN + 1];                            // aligned (ceil4) offsets
__device__ int g_cur[MAXN];
__device__ __align__(16) int g_csr[MAXE];                  // src ids grouped by dst, pad slots = N
__device__ int g_pad_unused;

// ---------------- side stream + events ----------------
struct HxStreams {
    cudaStream_t s2;
    cudaEvent_t evFork, evJoin;
    HxStreams() {
        cudaStreamCreateWithFlags(&s2, cudaStreamNonBlocking);
        cudaEventCreateWithFlags(&evFork, cudaEventDisableTiming);
        cudaEventCreateWithFlags(&evJoin, cudaEventDisableTiming);
    }
};
static HxStreams g_hx;

// pack two floats to fp16x2 (a -> low, b -> high), as uint32
__device__ __forceinline__ uint32_t packh(float a, float b) {
    __half2 h = __floats2half2_rn(a, b);
    return *(uint32_t*)&h;
}
__device__ __forceinline__ float2 unpackh(uint32_t u) {
    __half2 h = *(__half2*)&u;
    return __half22float2(h);
}

// per-block idx-width detection (64 reads, L1-broadcast; no cross-kernel dep)
__device__ __forceinline__ int detect_idx64(const int* ei32, int n_check, int* s_is64) {
    if (threadIdx.x == 0) {
        int is64 = 1;
        for (int k = 0; k < n_check; k++)
            if (ei32[2 * k + 1] != 0) { is64 = 0; break; }
        *s_is64 = is64;
    }
    __syncthreads();
    return *s_is64;
}

// ---------------- zero: deg zeros + sentinel alpha row ----------------
__global__ void zero_kernel(int N) {
    int i = blockIdx.x * blockDim.x + threadIdx.x;
    if (i < N) g_deg[i] = 0;
    if (i == N) {
#pragma unroll
        for (int h = 0; h < H; h++) g_as[(size_t)N * H + h] = -CUDART_INF_F;
    }
}

// ---------------- wpack: W fp16 uint2 fragment pack (side stream) ----------------
__global__ void wpack_kernel(const float* __restrict__ W) {
    int i = blockIdx.x * blockDim.x + threadIdx.x;
    if (i >= 8192) return;
    int ks = i >> 10;
    int rem = i & 1023;
    int gnt = rem >> 5;
    int lane = rem & 31;
    int g = lane >> 2, tig = lane & 3;
    int n = gnt * 8 + g;
    int k0 = ks * 16 + tig * 2;
    float w00 = (k0     < F_IN) ? W[(k0)     * HC + n] : 0.0f;
    float w01 = (k0 + 1 < F_IN) ? W[(k0 + 1) * HC + n] : 0.0f;
    float w10 = (k0 + 8 < F_IN) ? W[(k0 + 8) * HC + n] : 0.0f;
    float w11 = (k0 + 9 < F_IN) ? W[(k0 + 9) * HC + n] : 0.0f;
    g_Wh[ks][gnt][lane] = make_uint2(packh(w00, w01), packh(w10, w11));
}

// ---------------- count in-degrees (dst half only, per-block detect) ----------------
__global__ void count_kernel(const void* __restrict__ ei, int E, int n_check) {
    __shared__ int s_is64;
    int idx64 = detect_idx64((const int*)ei, n_check, &s_is64);
    int i = blockIdx.x * blockDim.x + threadIdx.x;
    if (i >= E) return;
    int dst;
    if (idx64) dst = (int)((const long long*)ei)[(size_t)E + i];
    else       dst = ((const int*)ei)[E + i];
    atomicAdd(&g_deg[dst], 1);
}

// ---------------- single-kernel exclusive scan of ceil4(deg) -> g_off, g_cur ----------------
__device__ __forceinline__ int ceil4(int v) { return (v + 3) & ~3; }

__global__ void scan_kernel(int N) {
    __shared__ int sm[256];
    int b0 = blockIdx.x * SCHUNK;
    int t = threadIdx.x;

    int base_p = 0;
    for (int i = t * 4; i < b0; i += 1024) {
        int4 d = *(const int4*)&g_deg[i];
        base_p += ceil4(d.x) + ceil4(d.y) + ceil4(d.z) + ceil4(d.w);
    }
    sm[t] = base_p;
    __syncthreads();
    for (int o = 128; o > 0; o >>= 1) {
        if (t < o) sm[t] += sm[t + o];
        __syncthreads();
    }
    int base = sm[0];
    __syncthreads();

    const int PT = SCHUNK / 256;
    int cbase = b0 + t * PT;
    int loc[PT];
    int s = 0;
#pragma unroll
    for (int k = 0; k < PT; k++) {
        int i = cbase + k;
        loc[k] = s;
        if (i < N) s += ceil4(g_deg[i]);
    }
    sm[t] = s;
    __syncthreads();
    for (int o = 1; o < 256; o <<= 1) {
        int v = (t >= o) ? sm[t - o] : 0;
        __syncthreads();
        sm[t] += v;
        __syncthreads();
    }
    int tbase = base + ((t > 0) ? sm[t - 1] : 0);
#pragma unroll
    for (int k = 0; k < PT; k++) {
        int i = cbase + k;
        if (i < N) {
            int o = tbase + loc[k];
            g_off[i] = o;
            g_cur[i] = o;
            int d = g_deg[i];
            int c4 = ceil4(d);
            for (int q = d; q < c4; q++) g_csr[o + q] = N;
        }
    }
    if (blockIdx.x == gridDim.x - 1 && t == 255) g_off[N] = base + sm[255];
}

// ---------------- scatter src ids into CSR slots (per-block detect) ----------------
__global__ void scatter_kernel(const void* __restrict__ ei, int E, int n_check) {
    __shared__ int s_is64;
    int idx64 = detect_idx64((const int*)ei, n_check, &s_is64);
    int i = blockIdx.x * blockDim.x + threadIdx.x;
    if (i >= E) return;
    int src, dst;
    if (idx64) {
        const long long* p = (const long long*)ei;
        src = (int)p[i];
        dst = (int)p[(size_t)E + i];
    } else {
        const int* p = (const int*)ei;
        src = p[i];
        dst = p[E + i];
    }
    int pos = atomicAdd(&g_cur[dst], 1);
    g_csr[pos] = src;
}

// ---------------- gemm: HMMA fp16 2-term split (xh*wh + xl*wh), fp32 accum ----------------
__device__ __forceinline__ void mma_f16(float* d, uint32_t a0, uint32_t a1, uint32_t a2, uint32_t a3,
                                        uint32_t b0, uint32_t b1) {
    asm("mma.sync.aligned.m16n8k16.row.col.f32.f16.f16.f32 "
        "{%0,%1,%2,%3}, {%4,%5,%6,%7}, {%8,%9}, {%0,%1,%2,%3};"
        : "+f"(d[0]), "+f"(d[1]), "+f"(d[2]), "+f"(d[3])
        : "r"(a0), "r"(a1), "r"(a2), "r"(a3), "r"(b0), "r"(b1));
}

__global__ void __launch_bounds__(256, 2)
gemm_alpha_kernel(const float* __restrict__ x,
                  const float* __restrict__ att_src,
                  const float* __restrict__ att_dst,
                  int N) {
    __shared__ __align__(16) float xs[MROWS][XSW];
    int t = threadIdx.x;
    int w = t >> 5, lane = t & 31;
    int g = lane >> 2, tig = lane & 3;
    int mw = w >> 2, nw = w & 3;
    int row0 = blockIdx.x * MROWS;

    for (int i = t; i < MROWS * 128; i += 256) {
        int r = i >> 7, c = i & 127;
        int gr = row0 + r;
        xs[r][c] = (c < F_IN && gr < N) ? x[(size_t)gr * F_IN + c] : 0.0f;
    }
    __syncthreads();

    float d[2][8][4];
#pragma unroll
    for (int mt = 0; mt < 2; mt++)
#pragma unroll
        for (int nt = 0; nt < 8; nt++)
#pragma unroll
            for (int q = 0; q < 4; q++) d[mt][nt][q] = 0.0f;

    int ra0 = mw * 32 + g;       // mt=0 rows: ra0, ra0+8; mt=1: ra0+16, ra0+24

#pragma unroll
    for (int ks = 0; ks < 8; ks++) {
        int k0 = ks * 16 + tig * 2;
        uint32_t ah[2][4], al[2][4];
#pragma unroll
        for (int mt = 0; mt < 2; mt++) {
            int ra = ra0 + mt * 16;
            float2 xa = *(const float2*)&xs[ra][k0];
            float2 xb = *(const float2*)&xs[ra + 8][k0];
            float2 xc = *(const float2*)&xs[ra][k0 + 8];
            float2 xd = *(const float2*)&xs[ra + 8][k0 + 8];
            ah[mt][0] = packh(xa.x, xa.y);
            ah[mt][1] = packh(xb.x, xb.y);
            ah[mt][2] = packh(xc.x, xc.y);
            ah[mt][3] = packh(xd.x, xd.y);
            float2 fa0 = unpackh(ah[mt][0]);
            float2 fa1 = unpackh(ah[mt][1]);
            float2 fa2 = unpackh(ah[mt][2]);
            float2 fa3 = unpackh(ah[mt][3]);
            al[mt][0] = packh(xa.x - fa0.x, xa.y - fa0.y);
            al[mt][1] = packh(xb.x - fa1.x, xb.y - fa1.y);
            al[mt][2] = packh(xc.x - fa2.x, xc.y - fa2.y);
            al[mt][3] = packh(xd.x - fa3.x, xd.y - fa3.y);
        }
#pragma unroll
        for (int nt = 0; nt < 8; nt++) {
            uint2 bw = g_Wh[ks][nw * 8 + nt][lane];
#pragma unroll
            for (int mt = 0; mt < 2; mt++) {
                mma_f16(d[mt][nt], ah[mt][0], ah[mt][1], ah[mt][2], ah[mt][3], bw.x, bw.y); // xh*wh
                mma_f16(d[mt][nt], al[mt][0], al[mt][1], al[mt][2], al[mt][3], bw.x, bw.y); // xl*wh
            }
        }
    }

    // epilogue: fp16 xt stores + per-(row, head) alpha partials, per m-tile
    __half2* xt2 = (__half2*)g_xt_h;
    float pS[2][2][2] = {};   // [mt][rowsel][headsel]
    float pD[2][2][2] = {};

#pragma unroll
    for (int nt = 0; nt < 8; nt++) {
        int col = nw * 64 + nt * 8 + tig * 2;
        int hs = nt >> 2;
        float s0 = __ldg(&att_src[col]);
        float s1 = __ldg(&att_src[col + 1]);
        float t0 = __ldg(&att_dst[col]);
        float t1 = __ldg(&att_dst[col + 1]);
#pragma unroll
        for (int mt = 0; mt < 2; mt++) {
            int gr0 = row0 + ra0 + mt * 16;
            int gr1 = gr0 + 8;
            pS[mt][0][hs] += d[mt][nt][0] * s0 + d[mt][nt][1] * s1;
            pS[mt][1][hs] += d[mt][nt][2] * s0 + d[mt][nt][3] * s1;
            pD[mt][0][hs] += d[mt][nt][0] * t0 + d[mt][nt][1] * t1;
            pD[mt][1][hs] += d[mt][nt][2] * t0 + d[mt][nt][3] * t1;
            if (gr0 < N) xt2[(size_t)gr0 * 128 + (col >> 1)] = __floats2half2_rn(d[mt][nt][0], d[mt][nt][1]);
            if (gr1 < N) xt2[(size_t)gr1 * 128 + (col >> 1)] = __floats2half2_rn(d[mt][nt][2], d[mt][nt][3]);
        }
    }

#pragma unroll
    for (int mt = 0; mt < 2; mt++)
#pragma unroll
        for (int rs = 0; rs < 2; rs++)
#pragma unroll
            for (int hsl = 0; hsl < 2; hsl++) {
                float v1 = pS[mt][rs][hsl];
                v1 += __shfl_xor_sync(0xffffffffu, v1, 1);
                v1 += __shfl_xor_sync(0xffffffffu, v1, 2);
                pS[mt][rs][hsl] = v1;
                float v2 = pD[mt][rs][hsl];
                v2 += __shfl_xor_sync(0xffffffffu, v2, 1);
                v2 += __shfl_xor_sync(0xffffffffu, v2, 2);
                pD[mt][rs][hsl] = v2;
            }

    if (tig == 0) {
#pragma unroll
        for (int mt = 0; mt < 2; mt++)
#pragma unroll
            for (int rs = 0; rs < 2; rs++) {
                int gr = row0 + ra0 + mt * 16 + rs * 8;
                if (gr < N) {
#pragma unroll
                    for (int hsl = 0; hsl < 2; hsl++) {
                        int h = nw * 2 + hsl;
                        g_as[(size_t)gr * H + h] = pS[mt][rs][hsl];
                        g_ad[(size_t)gr * H + h] = pD[mt][rs][hsl];
                    }
                }
            }
    }
}

// ---------------- fused gather-aggregate + softmax + head-mean + bias + relu ----------------
__device__ __forceinline__ void acc_row(const float4& raw, float ev, float* acc) {
    const __half2* hp = (const __half2*)&raw;
    float2 f0 = __half22float2(hp[0]);
    float2 f1 = __half22float2(hp[1]);
    float2 f2 = __half22float2(hp[2]);
    float2 f3 = __half22float2(hp[3]);
    acc[0] = fmaf(ev, f0.x, acc[0]); acc[1] = fmaf(ev, f0.y, acc[1]);
    acc[2] = fmaf(ev, f1.x, acc[2]); acc[3] = fmaf(ev, f1.y, acc[3]);
    acc[4] = fmaf(ev, f2.x, acc[4]); acc[5] = fmaf(ev, f2.y, acc[5]);
    acc[6] = fmaf(ev, f3.x, acc[6]); acc[7] = fmaf(ev, f3.y, acc[7]);
}

__global__ void agg_kernel(const float* __restrict__ bias,
                           float* __restrict__ out, int N) {
    int gw = (blockIdx.x * blockDim.x + threadIdx.x) >> 5;
    int lane = threadIdx.x & 31;
    if (gw >= N) return;
    int n = gw;
    int h = lane >> 2;

    const char* asb = (const char*)g_as;
    const char* xtb = (const char*)g_xt_h;
    int hoff = h << 2;
    int loff = lane << 4;

    float ad_h = g_ad[(size_t)n * H + h];

    float a = *(const float*)(asb + (((unsigned)n << 5) + hoff)) + ad_h;
    a = (a > 0.0f) ? a : NEG_SLOPE * a;
    float e = __expf(a);
    float s = e;

    float acc[8] = {0, 0, 0, 0, 0, 0, 0, 0};
    {
        float4 raw = *(const float4*)(xtb + ((unsigned)n << 9) + loff);
        acc_row(raw, e, acc);
    }

    int beg = g_off[n];
    int end = g_off[n + 1];
    for (int p = beg; p < end; p += 4) {
        int4 sv = *(const int4*)(g_csr + p);
        float a0 = *(const float*)(asb + (((unsigned)sv.x << 5) + hoff)) + ad_h;
        float a1 = *(const float*)(asb + (((unsigned)sv.y << 5) + hoff)) + ad_h;
        float a2 = *(const float*)(asb + (((unsigned)sv.z << 5) + hoff)) + ad_h;
        float a3 = *(const float*)(asb + (((unsigned)sv.w << 5) + hoff)) + ad_h;
        a0 = (a0 > 0.0f) ? a0 : NEG_SLOPE * a0;
        a1 = (a1 > 0.0f) ? a1 : NEG_SLOPE * a1;
        a2 = (a2 > 0.0f) ? a2 : NEG_SLOPE * a2;
        a3 = (a3 > 0.0f) ? a3 : NEG_SLOPE * a3;
        float e0 = __expf(a0);
        float e1 = __expf(a1);
        float e2 = __expf(a2);
        float e3 = __expf(a3);
        s += (e0 + e1) + (e2 + e3);
        float4 r0 = *(const float4*)(xtb + ((unsigned)sv.x << 9) + loff);
        float4 r1 = *(const float4*)(xtb + ((unsigned)sv.y << 9) + loff);
        float4 r2 = *(const float4*)(xtb + ((unsigned)sv.z << 9) + loff);
        float4 r3 = *(const float4*)(xtb + ((unsigned)sv.w << 9) + loff);
        acc_row(r0, e0, acc);
        acc_row(r1, e1, acc);
        acc_row(r2, e2, acc);
        acc_row(r3, e3, acc);
    }

    float inv = 1.0f / (s + 1e-16f);
    float r[8];
#pragma unroll
    for (int i = 0; i < 8; i++) r[i] = acc[i] * inv;

#pragma unroll
    for (int i = 0; i < 8; i++) {
        r[i] += __shfl_xor_sync(0xffffffffu, r[i], 4);
        r[i] += __shfl_xor_sync(0xffffffffu, r[i], 8);
        r[i] += __shfl_xor_sync(0xffffffffu, r[i], 16);
    }

    if (lane < 4) {
        float o[8];
#pragma unroll
        for (int i = 0; i < 8; i++) {
            float v = r[i] * 0.125f + bias[lane * 8 + i];
            o[i] = (v > 0.0f) ? v : 0.0f;
        }
        float4* orow = (float4*)(out + (size_t)n * C + lane * 8);
        orow[0] = make_float4(o[0], o[1], o[2], o[3]);
        orow[1] = make_float4(o[4], o[5], o[6], o[7]);
    }
}

// ---------------- launch: zero, count || (wpack, gemm), scan, scatter, agg ----------------
extern "C" void kernel_launch(void* const* d_in, const int* in_sizes, int n_in,
                              void* d_out, int out_size) {
    const float* x       = (const float*)d_in[0];
    const void*  ei      = d_in[1];
    const float* W       = (const float*)d_in[2];
    const float* att_src = (const float*)d_in[3];
    const float* att_dst = (const float*)d_in[4];
    const float* bias    = (const float*)d_in[5];

    int N = in_sizes[0] / F_IN;
    int E = in_sizes[1] / 2;
    int n_check = E > 64 ? 64 : E;

    // fork side stream immediately — wpack+gemm run concurrent with the CSR chain
    cudaEventRecord(g_hx.evFork, 0);
    cudaStreamWaitEvent(g_hx.s2, g_hx.evFork, 0);

    // (1) zero (main): deg zeros + sentinel alpha row
    zero_kernel<<<(N + 256) / 256, 256>>>(N);

    // (2) count (main)
    count_kernel<<<(E + 255) / 256, 256>>>(ei, E, n_check);

    // (3) wpack, (4) gemm  [side stream — gemm in profile slot 4]
    wpack_kernel<<<32, 256, 0, g_hx.s2>>>(W);
    gemm_alpha_kernel<<<(N + MROWS - 1) / MROWS, 256, 0, g_hx.s2>>>(x, att_src, att_dst, N);
    cudaEventRecord(g_hx.evJoin, g_hx.s2);

    // (5) scan, (6) scatter  [main]
    int NB = (N + SCHUNK - 1) / SCHUNK;
    scan_kernel<<<NB, 256>>>(N);
    scatter_kernel<<<(E + 255) / 256, 256>>>(ei, E, n_check);

    // (7) aggregate (joins gemm)
    cudaStreamWaitEvent(0, g_hx.evJoin, 0);
    agg_kernel<<<(N + 7) / 8, 256>>>(bias, (float*)d_out, N);
}